// round 7
// baseline (speedup 1.0000x reference)
#include <cuda_runtime.h>
#include <cuda_fp16.h>
#include <cstdint>

// ---------------- problem constants ----------------
#define N_NODES 8192
#define F_IN    256
#define D_OUT   64
#define LOG2E   1.4426950408889634f
#define PSCALE  0x1p-8f   // global 2^-8 on P; cancels in softmax

// ---------------- device scratch (no allocation allowed) ----------------
__device__ float g_h[N_NODES * D_OUT];
__device__ float g_e1[N_NODES];
__device__ float g_e2[N_NODES];
__device__ __half g_ht[D_OUT * N_NODES];    // H^T fp16, [d][j]

// ---------------- helpers ----------------
__device__ __forceinline__ uint32_t smem_u32(const void* p) {
    uint32_t a;
    asm("{ .reg .u64 t; cvta.to.shared.u64 t, %1; cvt.u32.u64 %0, t; }"
        : "=r"(a) : "l"(p));
    return a;
}
__device__ __forceinline__ uint32_t pack_f16x2(float lo, float hi) {
    uint32_t r;
    asm("cvt.rn.f16x2.f32 %0, %1, %2;" : "=r"(r) : "f"(hi), "f"(lo));
    return r;
}
__device__ __forceinline__ float ex2(float x) {
    float r;
    asm("ex2.approx.ftz.f32 %0, %1;" : "=f"(r) : "f"(x));
    return r;
}
__device__ __forceinline__ unsigned long long pk2(float lo, float hi) {
    unsigned long long r;
    asm("mov.b64 %0, {%1, %2};" : "=l"(r) : "f"(lo), "f"(hi));
    return r;
}
__device__ __forceinline__ void upk2(float& lo, float& hi, unsigned long long v) {
    asm("mov.b64 {%0, %1}, %2;" : "=f"(lo), "=f"(hi) : "l"(v));
}
__device__ __forceinline__ void add2(unsigned long long& d, unsigned long long a) {
    asm("add.rn.f32x2 %0, %0, %1;" : "+l"(d) : "l"(a));
}
__device__ __forceinline__ void ldsm_x4(uint32_t (&r)[4], uint32_t addr) {
    asm volatile("ldmatrix.sync.aligned.m8n8.x4.shared.b16 {%0,%1,%2,%3}, [%4];"
                 : "=r"(r[0]), "=r"(r[1]), "=r"(r[2]), "=r"(r[3]) : "r"(addr));
}
__device__ __forceinline__ void mma16816(float (&c)[4], const uint32_t (&a)[4],
                                         const uint32_t* b) {
    asm volatile("mma.sync.aligned.m16n8k16.row.col.f32.f16.f16.f32 "
        "{%0,%1,%2,%3}, {%4,%5,%6,%7}, {%8,%9}, {%0,%1,%2,%3};"
        : "+f"(c[0]), "+f"(c[1]), "+f"(c[2]), "+f"(c[3])
        : "r"(a[0]), "r"(a[1]), "r"(a[2]), "r"(a[3]), "r"(b[0]), "r"(b[1]));
}

// ---------------- kernel 1: h = x @ trans (vectorized LDS inner loop) ----------------
__global__ void k_h_gemm(const float* __restrict__ x,
                         const float* __restrict__ trans) {
    __shared__ float xs[16 * F_IN];
    __shared__ float ts[64 * D_OUT];
    __shared__ float trs[64 * 17];

    const int t = threadIdx.x;
    const int d = t & 63;
    const int rg = t >> 6;
    const int ibase = blockIdx.x * 16;

    {
        const float4* xg4 = reinterpret_cast<const float4*>(x) + (size_t)ibase * (F_IN / 4);
        float4* xs4 = reinterpret_cast<float4*>(xs);
        #pragma unroll
        for (int q = 0; q < 4; q++) xs4[t + q * 256] = xg4[t + q * 256];
    }

    float acc[4] = {0.f, 0.f, 0.f, 0.f};

    for (int kc = 0; kc < 4; kc++) {
        {
            const float4* tg4 = reinterpret_cast<const float4*>(trans) + kc * 1024;
            float4* ts4 = reinterpret_cast<float4*>(ts);
            #pragma unroll
            for (int q = 0; q < 4; q++) ts4[t + q * 256] = tg4[t + q * 256];
        }
        __syncthreads();
        #pragma unroll 4
        for (int k4 = 0; k4 < 16; k4++) {
            float4 xv[4];
            #pragma unroll
            for (int r = 0; r < 4; r++)
                xv[r] = *reinterpret_cast<const float4*>(
                    &xs[(rg * 4 + r) * F_IN + kc * 64 + k4 * 4]);
            #pragma unroll
            for (int kk = 0; kk < 4; kk++) {
                const float tv = ts[(k4 * 4 + kk) * 64 + d];
                #pragma unroll
                for (int r = 0; r < 4; r++)
                    acc[r] = fmaf(reinterpret_cast<const float*>(&xv[r])[kk],
                                  tv, acc[r]);
            }
        }
        __syncthreads();
    }

    #pragma unroll
    for (int r = 0; r < 4; r++) {
        g_h[(size_t)(ibase + rg * 4 + r) * D_OUT + d] = acc[r];
        trs[d * 17 + rg * 4 + r] = acc[r];
    }
    __syncthreads();

    // fp16 transposed write: thread -> (dd, 4 rows)
    {
        const int dd = t >> 2;
        const int seg = t & 3;
        const float v0 = trs[dd * 17 + seg * 4 + 0];
        const float v1 = trs[dd * 17 + seg * 4 + 1];
        const float v2 = trs[dd * 17 + seg * 4 + 2];
        const float v3 = trs[dd * 17 + seg * 4 + 3];
        const uint32_t h01 = pack_f16x2(v0, v1);
        const uint32_t h23 = pack_f16x2(v2, v3);
        *reinterpret_cast<uint2*>(g_ht + (size_t)dd * N_NODES + ibase + seg * 4) =
            make_uint2(h01, h23);
    }
}

// ---------------- kernel 2: e1/e2 projections ----------------
__global__ void k_e(const float* __restrict__ attn) {
    const int wid = threadIdx.x >> 5;
    const int lane = threadIdx.x & 31;
    const int row = blockIdx.x * 8 + wid;

    const float h0 = g_h[(size_t)row * D_OUT + lane];
    const float h1 = g_h[(size_t)row * D_OUT + lane + 32];
    float v1 = h0 * attn[lane] + h1 * attn[lane + 32];
    float v2 = h0 * attn[64 + lane] + h1 * attn[96 + lane];
    #pragma unroll
    for (int o = 16; o > 0; o >>= 1) {
        v1 += __shfl_xor_sync(0xffffffffu, v1, o);
        v2 += __shfl_xor_sync(0xffffffffu, v2, o);
    }
    if (lane == 0) { g_e1[row] = v1; g_e2[row] = v2; }
}

// ---------------- kernel 3: warp-specialized fused attention (depth-2 prefetch) ----------------
// CTA: 64 rows x full 8192 j. Tile: 64 rows x 64 j. 128 tiles.
#define PROW 144
#define PHI_OFF(b) ((b) * 9216)               // P: 2 x 9 KB
#define BHI_OFF(b) (18432 + (b) * 9216)       // H: 2 x 9 KB
#define E2S_OFF    36864                      // e2 full range: 32 KB
#define SMEM_BYTES (36864 + 32768 + 128)

#define NTILES 128

__global__ __launch_bounds__(512, 1)
void k_attn_ws(const int* __restrict__ mask, float* __restrict__ out) {
    extern __shared__ char dsmem[];
    __shared__ float zs[64];

    const int t = threadIdx.x;
    const int lane = t & 31;
    const int w = t >> 5;
    const int ibase = blockIdx.x * 64;

    const uint32_t sbase = smem_u32(dsmem);
    const uint32_t abase = (sbase + 127) & ~127u;
    char* ab = dsmem + (abase - sbase);

    // stage e2 (prescaled by log2e): all 512 threads, 2048 float4
    {
        float4* dst = reinterpret_cast<float4*>(ab + E2S_OFF);
        const float4* src = reinterpret_cast<const float4*>(g_e2);
        #pragma unroll
        for (int q = 0; q < 4; q++) {
            float4 v = src[t + q * 512];
            v.x *= LOG2E; v.y *= LOG2E; v.z *= LOG2E; v.w *= LOG2E;
            dst[t + q * 512] = v;
        }
    }
    const float* e2s = reinterpret_cast<const float*>(ab + E2S_OFF);

    // ============ producer state (warps 0-7, t < 256) ============
    const int prow = t >> 2;            // row within block (0..63)
    const int j0 = (t & 3) << 4;        // 16 j per thread
    const float ei = g_e1[ibase + prow] * LOG2E;

    const uint4* mrow_p = reinterpret_cast<const uint4*>(
        mask + (size_t)(ibase + prow) * N_NODES + j0);
    const int hd = t >> 2;              // d row 0..63
    const int hj = t & 3;               // j segment *16
    const __half* hbase = g_ht + (size_t)hd * N_NODES + hj * 16;

    // depth-2 prefetch register sets (set s covers tiles with (tile&1)==s)
    uint4 mreg[2][4];
    uint4 hA[2], hB[2];
    unsigned long long zacc = 0ull;

    // ============ consumer state (warps 8-15) ============
    const int wc = w - 8;
    const int mrow = (wc & 3) * 16;     // 4 m-groups of 16
    const int nc0 = (wc >> 2) * 32;     // 2 n-groups of 32
    const uint32_t a_base = (uint32_t)((mrow + (lane & 15)) * PROW + ((lane >> 4) << 4));
    const uint32_t b_row = (uint32_t)(((lane >> 4) << 3) + (lane & 7));
    const uint32_t b_byt = (uint32_t)(((lane >> 3) & 1) << 4);
    const uint32_t b_base0 = (uint32_t)((nc0 + b_row) * PROW + b_byt);
    const uint32_t b_base1 = (uint32_t)((nc0 + 16 + b_row) * PROW + b_byt);

    float acc[4][4];
    #pragma unroll
    for (int nf = 0; nf < 4; nf++)
        #pragma unroll
        for (int c = 0; c < 4; c++) acc[nf][c] = 0.f;

    // prologue prefetch (producers): tiles 0 and 1
    if (w < 8) {
        #pragma unroll
        for (int s = 0; s < 2; s++) {
            const uint4* mp = mrow_p + s * 16;
            #pragma unroll
            for (int g = 0; g < 4; g++) mreg[s][g] = mp[g];
            hA[s] = *reinterpret_cast<const uint4*>(hbase + s * 64);
            hB[s] = *reinterpret_cast<const uint4*>(hbase + s * 64 + 8);
        }
    }

    for (int it = 0; it <= NTILES; it++) {
        __syncthreads();
        if (w < 8) {
            if (it < NTILES) {
                const int buf = it & 1;
                // stage H tile from set `buf`
                {
                    const uint32_t so = (uint32_t)(hd * PROW + hj * 32);
                    *reinterpret_cast<uint4*>(ab + BHI_OFF(buf) + so) = hA[buf];
                    *reinterpret_cast<uint4*>(ab + BHI_OFF(buf) + so + 16) = hB[buf];
                }
                // compute P (16 elems) from mask set `buf`
                {
                    const float* e2p = e2s + it * 64 + j0;
                    uint32_t hiu[8];
                    #pragma unroll
                    for (int g = 0; g < 4; g++) {
                        const float4 ev = reinterpret_cast<const float4*>(e2p)[g];
                        const uint4 mm = mreg[buf][g];
                        const float e4[4] = {ev.x, ev.y, ev.z, ev.w};
                        const uint32_t m4[4] = {mm.x, mm.y, mm.z, mm.w};
                        float p[4];
                        #pragma unroll
                        for (int k = 0; k < 4; k++) {
                            float s = ei + e4[k];
                            s = fmaxf(s, 0.2f * s);
                            const float pe = ex2(s) * PSCALE;
                            p[k] = __uint_as_float(__float_as_uint(pe) &
                                                   (uint32_t)(-(int)m4[k]));
                        }
                        add2(zacc, pk2(p[0], p[1]));
                        add2(zacc, pk2(p[2], p[3]));
                        hiu[g * 2]     = pack_f16x2(p[0], p[1]);
                        hiu[g * 2 + 1] = pack_f16x2(p[2], p[3]);
                    }
                    const uint32_t ro = (uint32_t)(prow * PROW + j0 * 2);
                    *reinterpret_cast<uint4*>(ab + PHI_OFF(buf) + ro) =
                        make_uint4(hiu[0], hiu[1], hiu[2], hiu[3]);
                    *reinterpret_cast<uint4*>(ab + PHI_OFF(buf) + ro + 16) =
                        make_uint4(hiu[4], hiu[5], hiu[6], hiu[7]);
                }
                // prefetch tile it+2 into set `buf` (same parity; wrap keeps valid)
                {
                    int nt = it + 2;
                    if (nt >= NTILES) nt -= NTILES;
                    const uint4* mp = mrow_p + nt * 16;
                    #pragma unroll
                    for (int g = 0; g < 4; g++) mreg[buf][g] = mp[g];
                    hA[buf] = *reinterpret_cast<const uint4*>(hbase + nt * 64);
                    hB[buf] = *reinterpret_cast<const uint4*>(hbase + nt * 64 + 8);
                }
            }
        } else {
            if (it >= 1) {
                const int buf = (it - 1) & 1;
                const uint32_t phi = abase + PHI_OFF(buf);
                const uint32_t bhi = abase + BHI_OFF(buf);
                #pragma unroll
                for (int kk = 0; kk < 4; kk++) {
                    const uint32_t off = (uint32_t)(kk * 32);
                    uint32_t ah[4], bh0[4], bh1[4];
                    ldsm_x4(ah, phi + a_base + off);
                    ldsm_x4(bh0, bhi + b_base0 + off);
                    ldsm_x4(bh1, bhi + b_base1 + off);
                    mma16816(acc[0], ah, &bh0[0]);
                    mma16816(acc[1], ah, &bh0[2]);
                    mma16816(acc[2], ah, &bh1[0]);
                    mma16816(acc[3], ah, &bh1[2]);
                }
            }
        }
    }

    // ---- epilogue ----
    if (w < 8) {
        float zlo, zhi;
        upk2(zlo, zhi, zacc);
        float zsum = zlo + zhi;
        zsum += __shfl_xor_sync(0xffffffffu, zsum, 1);
        zsum += __shfl_xor_sync(0xffffffffu, zsum, 2);
        if ((t & 3) == 0) zs[prow] = zsum;
    }
    __syncthreads();
    if (w >= 8) {
        const int r0 = mrow + (lane >> 2);
        const float rz0 = 1.0f / zs[r0];
        const float rz1 = 1.0f / zs[r0 + 8];
        #pragma unroll
        for (int nf = 0; nf < 4; nf++) {
            const int col = nc0 + nf * 8 + (lane & 3) * 2;
            *reinterpret_cast<float2*>(
                out + (size_t)(ibase + r0) * D_OUT + col) =
                make_float2(acc[nf][0] * rz0, acc[nf][1] * rz0);
            *reinterpret_cast<float2*>(
                out + (size_t)(ibase + r0 + 8) * D_OUT + col) =
                make_float2(acc[nf][2] * rz1, acc[nf][3] * rz1);
        }
    }
}

// ---------------- launch ----------------
extern "C" void kernel_launch(void* const* d_in, const int* in_sizes, int n_in,
                              void* d_out, int out_size) {
    const float* x     = (const float*)d_in[0];   // [8192, 256]
    const int*   mask  = (const int*)d_in[1];     // [8192, 8192]
    const float* trans = (const float*)d_in[2];   // [256, 64]
    const float* attn  = (const float*)d_in[3];   // [128, 1]
    float* out = (float*)d_out;                   // [8192, 64]

    cudaFuncSetAttribute(k_attn_ws, cudaFuncAttributeMaxDynamicSharedMemorySize,
                         SMEM_BYTES);

    k_h_gemm<<<N_NODES / 16, 256>>>(x, trans);
    k_e<<<N_NODES / 8, 256>>>(attn);
    k_attn_ws<<<N_NODES / 64, 512, SMEM_BYTES>>>(mask, out);
}

// round 8
// speedup vs baseline: 1.1419x; 1.1419x over previous
#include <cuda_runtime.h>
#include <cuda_fp16.h>
#include <cstdint>

// ---------------- problem constants ----------------
#define N_NODES 8192
#define F_IN    256
#define D_OUT   64
#define LOG2E   1.4426950408889634f
#define PSCALE  0x1p-8f   // global 2^-8 on P; cancels in softmax

// ---------------- device scratch (no allocation allowed) ----------------
__device__ float g_h[N_NODES * D_OUT];
__device__ float g_e1[N_NODES];
__device__ float g_e2[N_NODES];
__device__ __half g_ht[D_OUT * N_NODES];    // H^T fp16, [d][j]

// ---------------- helpers ----------------
__device__ __forceinline__ uint32_t smem_u32(const void* p) {
    uint32_t a;
    asm("{ .reg .u64 t; cvta.to.shared.u64 t, %1; cvt.u32.u64 %0, t; }"
        : "=r"(a) : "l"(p));
    return a;
}
__device__ __forceinline__ uint32_t pack_f16x2(float lo, float hi) {
    uint32_t r;
    asm("cvt.rn.f16x2.f32 %0, %1, %2;" : "=r"(r) : "f"(hi), "f"(lo));
    return r;
}
__device__ __forceinline__ float ex2(float x) {
    float r;
    asm("ex2.approx.ftz.f32 %0, %1;" : "=f"(r) : "f"(x));
    return r;
}
__device__ __forceinline__ unsigned long long pk2(float lo, float hi) {
    unsigned long long r;
    asm("mov.b64 %0, {%1, %2};" : "=l"(r) : "f"(lo), "f"(hi));
    return r;
}
__device__ __forceinline__ void upk2(float& lo, float& hi, unsigned long long v) {
    asm("mov.b64 {%0, %1}, %2;" : "=f"(lo), "=f"(hi) : "l"(v));
}
__device__ __forceinline__ void add2(unsigned long long& d, unsigned long long a) {
    asm("add.rn.f32x2 %0, %0, %1;" : "+l"(d) : "l"(a));
}
__device__ __forceinline__ void ldsm_x4(uint32_t (&r)[4], uint32_t addr) {
    asm volatile("ldmatrix.sync.aligned.m8n8.x4.shared.b16 {%0,%1,%2,%3}, [%4];"
                 : "=r"(r[0]), "=r"(r[1]), "=r"(r[2]), "=r"(r[3]) : "r"(addr));
}
__device__ __forceinline__ void mma16816(float (&c)[4], const uint32_t (&a)[4],
                                         const uint32_t* b) {
    asm volatile("mma.sync.aligned.m16n8k16.row.col.f32.f16.f16.f32 "
        "{%0,%1,%2,%3}, {%4,%5,%6,%7}, {%8,%9}, {%0,%1,%2,%3};"
        : "+f"(c[0]), "+f"(c[1]), "+f"(c[2]), "+f"(c[3])
        : "r"(a[0]), "r"(a[1]), "r"(a[2]), "r"(a[3]), "r"(b[0]), "r"(b[1]));
}

// ---------------- kernel 1: h = x @ trans ----------------
__global__ void k_h_gemm(const float* __restrict__ x,
                         const float* __restrict__ trans) {
    __shared__ float xs[16 * F_IN];
    __shared__ float ts[64 * D_OUT];
    __shared__ float trs[64 * 17];

    const int t = threadIdx.x;
    const int d = t & 63;
    const int rg = t >> 6;
    const int ibase = blockIdx.x * 16;

    {
        const float4* xg4 = reinterpret_cast<const float4*>(x) + (size_t)ibase * (F_IN / 4);
        float4* xs4 = reinterpret_cast<float4*>(xs);
        #pragma unroll
        for (int q = 0; q < 4; q++) xs4[t + q * 256] = xg4[t + q * 256];
    }

    float acc[4] = {0.f, 0.f, 0.f, 0.f};

    for (int kc = 0; kc < 4; kc++) {
        {
            const float4* tg4 = reinterpret_cast<const float4*>(trans) + kc * 1024;
            float4* ts4 = reinterpret_cast<float4*>(ts);
            #pragma unroll
            for (int q = 0; q < 4; q++) ts4[t + q * 256] = tg4[t + q * 256];
        }
        __syncthreads();
        #pragma unroll 4
        for (int k4 = 0; k4 < 16; k4++) {
            float4 xv[4];
            #pragma unroll
            for (int r = 0; r < 4; r++)
                xv[r] = *reinterpret_cast<const float4*>(
                    &xs[(rg * 4 + r) * F_IN + kc * 64 + k4 * 4]);
            #pragma unroll
            for (int kk = 0; kk < 4; kk++) {
                const float tv = ts[(k4 * 4 + kk) * 64 + d];
                #pragma unroll
                for (int r = 0; r < 4; r++)
                    acc[r] = fmaf(reinterpret_cast<const float*>(&xv[r])[kk],
                                  tv, acc[r]);
            }
        }
        __syncthreads();
    }

    #pragma unroll
    for (int r = 0; r < 4; r++) {
        g_h[(size_t)(ibase + rg * 4 + r) * D_OUT + d] = acc[r];
        trs[d * 17 + rg * 4 + r] = acc[r];
    }
    __syncthreads();

    {
        const int dd = t >> 2;
        const int seg = t & 3;
        const float v0 = trs[dd * 17 + seg * 4 + 0];
        const float v1 = trs[dd * 17 + seg * 4 + 1];
        const float v2 = trs[dd * 17 + seg * 4 + 2];
        const float v3 = trs[dd * 17 + seg * 4 + 3];
        const uint32_t h01 = pack_f16x2(v0, v1);
        const uint32_t h23 = pack_f16x2(v2, v3);
        *reinterpret_cast<uint2*>(g_ht + (size_t)dd * N_NODES + ibase + seg * 4) =
            make_uint2(h01, h23);
    }
}

// ---------------- kernel 2: e1/e2 projections ----------------
__global__ void k_e(const float* __restrict__ attn) {
    const int wid = threadIdx.x >> 5;
    const int lane = threadIdx.x & 31;
    const int row = blockIdx.x * 8 + wid;

    const float h0 = g_h[(size_t)row * D_OUT + lane];
    const float h1 = g_h[(size_t)row * D_OUT + lane + 32];
    float v1 = h0 * attn[lane] + h1 * attn[lane + 32];
    float v2 = h0 * attn[64 + lane] + h1 * attn[96 + lane];
    #pragma unroll
    for (int o = 16; o > 0; o >>= 1) {
        v1 += __shfl_xor_sync(0xffffffffu, v1, o);
        v2 += __shfl_xor_sync(0xffffffffu, v2, o);
    }
    if (lane == 0) { g_e1[row] = v1; g_e2[row] = v2; }
}

// ---------------- kernel 3: warp-specialized fused attention (64x128 tiles) ----------------
// CTA: 64 rows x full 8192 j. Tile: 64 rows x 128 j. 64 tiles.
// Row stride 272 B (272 mod 128 = 16 -> conflict-free ldmatrix).
#define PROW 272
#define PHI_OFF(b) ((b) * 17408)               // P: 2 x 17 KB
#define BHI_OFF(b) (34816 + (b) * 17408)       // H: 2 x 17 KB
#define E2S_OFF    69632                       // e2 full range: 32 KB
#define SMEM_BYTES (69632 + 32768 + 128)

#define NT2 64   // 8192 / 128

__global__ __launch_bounds__(512, 1)
void k_attn_ws(const int* __restrict__ mask, float* __restrict__ out) {
    extern __shared__ char dsmem[];
    __shared__ float zs[64];

    const int t = threadIdx.x;
    const int lane = t & 31;
    const int w = t >> 5;
    const int ibase = blockIdx.x * 64;

    const uint32_t sbase = smem_u32(dsmem);
    const uint32_t abase = (sbase + 127) & ~127u;
    char* ab = dsmem + (abase - sbase);

    // stage e2 (prescaled by log2e): all 512 threads, 2048 float4
    {
        float4* dst = reinterpret_cast<float4*>(ab + E2S_OFF);
        const float4* src = reinterpret_cast<const float4*>(g_e2);
        #pragma unroll
        for (int q = 0; q < 4; q++) {
            float4 v = src[t + q * 512];
            v.x *= LOG2E; v.y *= LOG2E; v.z *= LOG2E; v.w *= LOG2E;
            dst[t + q * 512] = v;
        }
    }
    const float* e2s = reinterpret_cast<const float*>(ab + E2S_OFF);

    // ============ producer state (warps 0-7, t < 256) ============
    const int prow = t >> 2;            // row within block (0..63)
    const int j0 = (t & 3) << 5;        // 32 j per thread
    const float ei = g_e1[ibase + prow] * LOG2E;

    const uint4* mrow_p = reinterpret_cast<const uint4*>(
        mask + (size_t)(ibase + prow) * N_NODES + j0);   // tile stride: 32 uint4
    const int hd = t >> 2;              // d row 0..63
    const int hj = t & 3;               // j segment *32
    const __half* hbase = g_ht + (size_t)hd * N_NODES + hj * 32;

    uint4 mreg[8];                      // 32 mask ints (static indexing only)
    uint4 hreg[4];                      // 32 H halves
    unsigned long long zacc = 0ull;

    // ============ consumer state (warps 8-15) ============
    const int wc = w - 8;
    const int mrow = (wc & 3) * 16;     // 4 m-groups of 16
    const int nc0 = (wc >> 2) * 32;     // 2 n-groups of 32
    const uint32_t a_base = (uint32_t)((mrow + (lane & 15)) * PROW + ((lane >> 4) << 4));
    const uint32_t b_row = (uint32_t)(((lane >> 4) << 3) + (lane & 7));
    const uint32_t b_byt = (uint32_t)(((lane >> 3) & 1) << 4);
    const uint32_t b_base0 = (uint32_t)((nc0 + b_row) * PROW + b_byt);
    const uint32_t b_base1 = (uint32_t)((nc0 + 16 + b_row) * PROW + b_byt);

    float acc[4][4];
    #pragma unroll
    for (int nf = 0; nf < 4; nf++)
        #pragma unroll
        for (int c = 0; c < 4; c++) acc[nf][c] = 0.f;

    // prologue prefetch (producers, tile 0)
    if (w < 8) {
        #pragma unroll
        for (int g = 0; g < 8; g++) mreg[g] = mrow_p[g];
        #pragma unroll
        for (int g = 0; g < 4; g++)
            hreg[g] = *reinterpret_cast<const uint4*>(hbase + g * 8);
    }

    for (int it = 0; it <= NT2; it++) {
        __syncthreads();
        if (w < 8) {
            if (it < NT2) {
                const int buf = it & 1;
                // stage H tile
                {
                    const uint32_t so = (uint32_t)(hd * PROW + hj * 64);
                    #pragma unroll
                    for (int g = 0; g < 4; g++)
                        *reinterpret_cast<uint4*>(ab + BHI_OFF(buf) + so + g * 16) =
                            hreg[g];
                }
                // compute P (32 elems), single fp16
                {
                    const float* e2p = e2s + it * 128 + j0;
                    const uint32_t ro = (uint32_t)(prow * PROW + j0 * 2);
                    #pragma unroll
                    for (int g = 0; g < 8; g++) {
                        const float4 ev = reinterpret_cast<const float4*>(e2p)[g];
                        const uint4 mm = mreg[g];
                        const float e4[4] = {ev.x, ev.y, ev.z, ev.w};
                        const uint32_t m4[4] = {mm.x, mm.y, mm.z, mm.w};
                        float p[4];
                        #pragma unroll
                        for (int k = 0; k < 4; k++) {
                            float s = ei + e4[k];
                            s = fmaxf(s, 0.2f * s);
                            const float pe = ex2(s) * PSCALE;
                            p[k] = __uint_as_float(__float_as_uint(pe) &
                                                   (uint32_t)(-(int)m4[k]));
                        }
                        add2(zacc, pk2(p[0], p[1]));
                        add2(zacc, pk2(p[2], p[3]));
                        const uint32_t u01 = pack_f16x2(p[0], p[1]);
                        const uint32_t u23 = pack_f16x2(p[2], p[3]);
                        *reinterpret_cast<uint2*>(ab + PHI_OFF(buf) + ro + g * 8) =
                            make_uint2(u01, u23);
                    }
                }
                // prefetch next tile (wrap keeps addresses valid)
                {
                    const int nt = (it + 1 < NT2) ? it + 1 : 0;
                    const uint4* mp = mrow_p + nt * 32;
                    #pragma unroll
                    for (int g = 0; g < 8; g++) mreg[g] = mp[g];
                    #pragma unroll
                    for (int g = 0; g < 4; g++)
                        hreg[g] = *reinterpret_cast<const uint4*>(
                            hbase + nt * 128 + g * 8);
                }
            }
        } else {
            if (it >= 1) {
                const int buf = (it - 1) & 1;
                const uint32_t phi = abase + PHI_OFF(buf);
                const uint32_t bhi = abase + BHI_OFF(buf);
                #pragma unroll
                for (int kk = 0; kk < 8; kk++) {
                    const uint32_t off = (uint32_t)(kk * 32);
                    uint32_t ah[4], bh0[4], bh1[4];
                    ldsm_x4(ah, phi + a_base + off);
                    ldsm_x4(bh0, bhi + b_base0 + off);
                    ldsm_x4(bh1, bhi + b_base1 + off);
                    mma16816(acc[0], ah, &bh0[0]);
                    mma16816(acc[1], ah, &bh0[2]);
                    mma16816(acc[2], ah, &bh1[0]);
                    mma16816(acc[3], ah, &bh1[2]);
                }
            }
        }
    }

    // ---- epilogue ----
    if (w < 8) {
        float zlo, zhi;
        upk2(zlo, zhi, zacc);
        float zsum = zlo + zhi;
        zsum += __shfl_xor_sync(0xffffffffu, zsum, 1);
        zsum += __shfl_xor_sync(0xffffffffu, zsum, 2);
        if ((t & 3) == 0) zs[prow] = zsum;
    }
    __syncthreads();
    if (w >= 8) {
        const int r0 = mrow + (lane >> 2);
        const float rz0 = 1.0f / zs[r0];
        const float rz1 = 1.0f / zs[r0 + 8];
        #pragma unroll
        for (int nf = 0; nf < 4; nf++) {
            const int col = nc0 + nf * 8 + (lane & 3) * 2;
            *reinterpret_cast<float2*>(
                out + (size_t)(ibase + r0) * D_OUT + col) =
                make_float2(acc[nf][0] * rz0, acc[nf][1] * rz0);
            *reinterpret_cast<float2*>(
                out + (size_t)(ibase + r0 + 8) * D_OUT + col) =
                make_float2(acc[nf][2] * rz1, acc[nf][3] * rz1);
        }
    }
}

// ---------------- launch ----------------
extern "C" void kernel_launch(void* const* d_in, const int* in_sizes, int n_in,
                              void* d_out, int out_size) {
    const float* x     = (const float*)d_in[0];   // [8192, 256]
    const int*   mask  = (const int*)d_in[1];     // [8192, 8192]
    const float* trans = (const float*)d_in[2];   // [256, 64]
    const float* attn  = (const float*)d_in[3];   // [128, 1]
    float* out = (float*)d_out;                   // [8192, 64]

    cudaFuncSetAttribute(k_attn_ws, cudaFuncAttributeMaxDynamicSharedMemorySize,
                         SMEM_BYTES);

    k_h_gemm<<<N_NODES / 16, 256>>>(x, trans);
    k_e<<<N_NODES / 8, 256>>>(attn);
    k_attn_ws<<<N_NODES / 64, 512, SMEM_BYTES>>>(mask, out);
}

// round 9
// speedup vs baseline: 1.2659x; 1.1086x over previous
#include <cuda_runtime.h>
#include <cuda_fp16.h>
#include <cstdint>

// ---------------- problem constants ----------------
#define N_NODES 8192
#define F_IN    256
#define D_OUT   64
#define LOG2E   1.4426950408889634f
#define PSCALE  0x1p-8f   // global 2^-8 on P; cancels in softmax

// ---------------- device scratch (no allocation allowed) ----------------
__device__ float g_h[N_NODES * D_OUT];
__device__ float g_e1[N_NODES];
__device__ float g_e2[N_NODES];
__device__ __half g_ht[D_OUT * N_NODES];    // H^T fp16, [d][j]

// ---------------- helpers ----------------
__device__ __forceinline__ uint32_t smem_u32(const void* p) {
    uint32_t a;
    asm("{ .reg .u64 t; cvta.to.shared.u64 t, %1; cvt.u32.u64 %0, t; }"
        : "=r"(a) : "l"(p));
    return a;
}
__device__ __forceinline__ uint32_t pack_f16x2(float lo, float hi) {
    uint32_t r;
    asm("cvt.rn.f16x2.f32 %0, %1, %2;" : "=r"(r) : "f"(hi), "f"(lo));
    return r;
}
__device__ __forceinline__ float ex2(float x) {
    float r;
    asm("ex2.approx.ftz.f32 %0, %1;" : "=f"(r) : "f"(x));
    return r;
}
__device__ __forceinline__ unsigned long long pk2(float lo, float hi) {
    unsigned long long r;
    asm("mov.b64 %0, {%1, %2};" : "=l"(r) : "f"(lo), "f"(hi));
    return r;
}
__device__ __forceinline__ void upk2(float& lo, float& hi, unsigned long long v) {
    asm("mov.b64 {%0, %1}, %2;" : "=f"(lo), "=f"(hi) : "l"(v));
}
__device__ __forceinline__ void add2(unsigned long long& d, unsigned long long a) {
    asm("add.rn.f32x2 %0, %0, %1;" : "+l"(d) : "l"(a));
}
__device__ __forceinline__ void ldsm_x4(uint32_t (&r)[4], uint32_t addr) {
    asm volatile("ldmatrix.sync.aligned.m8n8.x4.shared.b16 {%0,%1,%2,%3}, [%4];"
                 : "=r"(r[0]), "=r"(r[1]), "=r"(r[2]), "=r"(r[3]) : "r"(addr));
}
__device__ __forceinline__ void mma16816(float (&c)[4], const uint32_t (&a)[4],
                                         const uint32_t* b) {
    asm volatile("mma.sync.aligned.m16n8k16.row.col.f32.f16.f16.f32 "
        "{%0,%1,%2,%3}, {%4,%5,%6,%7}, {%8,%9}, {%0,%1,%2,%3};"
        : "+f"(c[0]), "+f"(c[1]), "+f"(c[2]), "+f"(c[3])
        : "r"(a[0]), "r"(a[1]), "r"(a[2]), "r"(a[3]), "r"(b[0]), "r"(b[1]));
}
// named barriers: full[b] -> ids 1,2 ; free[b] -> ids 3,4
__device__ __forceinline__ void bar_sync(int id) {
    asm volatile("bar.sync %0, 512;" :: "r"(id) : "memory");
}
__device__ __forceinline__ void bar_arrive(int id) {
    asm volatile("bar.arrive %0, 512;" :: "r"(id) : "memory");
}

// ---------------- kernel 1: h = x @ trans ----------------
__global__ void k_h_gemm(const float* __restrict__ x,
                         const float* __restrict__ trans) {
    __shared__ float xs[16 * F_IN];
    __shared__ float ts[64 * D_OUT];
    __shared__ float trs[64 * 17];

    const int t = threadIdx.x;
    const int d = t & 63;
    const int rg = t >> 6;
    const int ibase = blockIdx.x * 16;

    {
        const float4* xg4 = reinterpret_cast<const float4*>(x) + (size_t)ibase * (F_IN / 4);
        float4* xs4 = reinterpret_cast<float4*>(xs);
        #pragma unroll
        for (int q = 0; q < 4; q++) xs4[t + q * 256] = xg4[t + q * 256];
    }

    float acc[4] = {0.f, 0.f, 0.f, 0.f};

    for (int kc = 0; kc < 4; kc++) {
        {
            const float4* tg4 = reinterpret_cast<const float4*>(trans) + kc * 1024;
            float4* ts4 = reinterpret_cast<float4*>(ts);
            #pragma unroll
            for (int q = 0; q < 4; q++) ts4[t + q * 256] = tg4[t + q * 256];
        }
        __syncthreads();
        #pragma unroll 4
        for (int k4 = 0; k4 < 16; k4++) {
            float4 xv[4];
            #pragma unroll
            for (int r = 0; r < 4; r++)
                xv[r] = *reinterpret_cast<const float4*>(
                    &xs[(rg * 4 + r) * F_IN + kc * 64 + k4 * 4]);
            #pragma unroll
            for (int kk = 0; kk < 4; kk++) {
                const float tv = ts[(k4 * 4 + kk) * 64 + d];
                #pragma unroll
                for (int r = 0; r < 4; r++)
                    acc[r] = fmaf(reinterpret_cast<const float*>(&xv[r])[kk],
                                  tv, acc[r]);
            }
        }
        __syncthreads();
    }

    #pragma unroll
    for (int r = 0; r < 4; r++) {
        g_h[(size_t)(ibase + rg * 4 + r) * D_OUT + d] = acc[r];
        trs[d * 17 + rg * 4 + r] = acc[r];
    }
    __syncthreads();

    {
        const int dd = t >> 2;
        const int seg = t & 3;
        const float v0 = trs[dd * 17 + seg * 4 + 0];
        const float v1 = trs[dd * 17 + seg * 4 + 1];
        const float v2 = trs[dd * 17 + seg * 4 + 2];
        const float v3 = trs[dd * 17 + seg * 4 + 3];
        const uint32_t h01 = pack_f16x2(v0, v1);
        const uint32_t h23 = pack_f16x2(v2, v3);
        *reinterpret_cast<uint2*>(g_ht + (size_t)dd * N_NODES + ibase + seg * 4) =
            make_uint2(h01, h23);
    }
}

// ---------------- kernel 2: e1/e2 projections ----------------
__global__ void k_e(const float* __restrict__ attn) {
    const int wid = threadIdx.x >> 5;
    const int lane = threadIdx.x & 31;
    const int row = blockIdx.x * 8 + wid;

    const float h0 = g_h[(size_t)row * D_OUT + lane];
    const float h1 = g_h[(size_t)row * D_OUT + lane + 32];
    float v1 = h0 * attn[lane] + h1 * attn[lane + 32];
    float v2 = h0 * attn[64 + lane] + h1 * attn[96 + lane];
    #pragma unroll
    for (int o = 16; o > 0; o >>= 1) {
        v1 += __shfl_xor_sync(0xffffffffu, v1, o);
        v2 += __shfl_xor_sync(0xffffffffu, v2, o);
    }
    if (lane == 0) { g_e1[row] = v1; g_e2[row] = v2; }
}

// ---------------- kernel 3: warp-specialized attention, named-barrier pipeline ----------------
// CTA: 64 rows x full 8192 j. Tile: 64 rows x 64 j. 128 tiles.
#define PROW 144
#define PHI_OFF(b) ((b) * 9216)               // P: 2 x 9 KB
#define BHI_OFF(b) (18432 + (b) * 9216)       // H: 2 x 9 KB
#define E2S_OFF    36864                      // e2 full range: 32 KB
#define SMEM_BYTES (36864 + 32768 + 128)

#define NTILES 128

__global__ __launch_bounds__(512, 1)
void k_attn_ws(const int* __restrict__ mask, float* __restrict__ out) {
    extern __shared__ char dsmem[];
    __shared__ float zs[64];

    const int t = threadIdx.x;
    const int lane = t & 31;
    const int w = t >> 5;
    const int ibase = blockIdx.x * 64;

    const uint32_t sbase = smem_u32(dsmem);
    const uint32_t abase = (sbase + 127) & ~127u;
    char* ab = dsmem + (abase - sbase);

    // stage e2 (prescaled by log2e): all 512 threads, 2048 float4
    {
        float4* dst = reinterpret_cast<float4*>(ab + E2S_OFF);
        const float4* src = reinterpret_cast<const float4*>(g_e2);
        #pragma unroll
        for (int q = 0; q < 4; q++) {
            float4 v = src[t + q * 512];
            v.x *= LOG2E; v.y *= LOG2E; v.z *= LOG2E; v.w *= LOG2E;
            dst[t + q * 512] = v;
        }
    }
    const float* e2s = reinterpret_cast<const float*>(ab + E2S_OFF);

    // ============ producer state (warps 0-7, t < 256) ============
    const int prow = t >> 2;            // row within block (0..63)
    const int j0 = (t & 3) << 4;        // 16 j per thread
    const float ei = g_e1[ibase + prow] * LOG2E;

    const uint4* mrow_p = reinterpret_cast<const uint4*>(
        mask + (size_t)(ibase + prow) * N_NODES + j0);
    const int hd = t >> 2;              // d row 0..63
    const int hj = t & 3;               // j segment *16
    const __half* hbase = g_ht + (size_t)hd * N_NODES + hj * 16;

    uint4 mreg[4];
    uint4 hA, hB;
    unsigned long long zacc = 0ull;

    // ============ consumer state (warps 8-15) ============
    const int wc = w - 8;
    const int mrow = (wc & 3) * 16;     // 4 m-groups of 16
    const int nc0 = (wc >> 2) * 32;     // 2 n-groups of 32
    const uint32_t a_base = (uint32_t)((mrow + (lane & 15)) * PROW + ((lane >> 4) << 4));
    const uint32_t b_row = (uint32_t)(((lane >> 4) << 3) + (lane & 7));
    const uint32_t b_byt = (uint32_t)(((lane >> 3) & 1) << 4);
    const uint32_t b_base0 = (uint32_t)((nc0 + b_row) * PROW + b_byt);
    const uint32_t b_base1 = (uint32_t)((nc0 + 16 + b_row) * PROW + b_byt);

    float acc[4][4];
    #pragma unroll
    for (int nf = 0; nf < 4; nf++)
        #pragma unroll
        for (int c = 0; c < 4; c++) acc[nf][c] = 0.f;

    // prologue prefetch (producers, tile 0)
    if (w < 8) {
        #pragma unroll
        for (int g = 0; g < 4; g++) mreg[g] = mrow_p[g];
        hA = *reinterpret_cast<const uint4*>(hbase);
        hB = *reinterpret_cast<const uint4*>(hbase + 8);
    }

    __syncthreads();   // e2s visible to everyone

    if (w < 8) {
        // ================= PRODUCER loop =================
        for (int it = 0; it < NTILES; it++) {
            const int buf = it & 1;
            if (it >= 2) bar_sync(3 + buf);        // wait buffer free
            // stage H tile
            {
                const uint32_t so = (uint32_t)(hd * PROW + hj * 32);
                *reinterpret_cast<uint4*>(ab + BHI_OFF(buf) + so) = hA;
                *reinterpret_cast<uint4*>(ab + BHI_OFF(buf) + so + 16) = hB;
            }
            // compute P (16 elems), single fp16
            {
                const float* e2p = e2s + it * 64 + j0;
                uint32_t hiu[8];
                #pragma unroll
                for (int g = 0; g < 4; g++) {
                    const float4 ev = reinterpret_cast<const float4*>(e2p)[g];
                    const uint4 mm = mreg[g];
                    const float e4[4] = {ev.x, ev.y, ev.z, ev.w};
                    const uint32_t m4[4] = {mm.x, mm.y, mm.z, mm.w};
                    float p[4];
                    #pragma unroll
                    for (int k = 0; k < 4; k++) {
                        float s = ei + e4[k];
                        s = fmaxf(s, 0.2f * s);
                        const float pe = ex2(s) * PSCALE;
                        p[k] = __uint_as_float(__float_as_uint(pe) &
                                               (uint32_t)(-(int)m4[k]));
                    }
                    add2(zacc, pk2(p[0], p[1]));
                    add2(zacc, pk2(p[2], p[3]));
                    hiu[g * 2]     = pack_f16x2(p[0], p[1]);
                    hiu[g * 2 + 1] = pack_f16x2(p[2], p[3]);
                }
                const uint32_t ro = (uint32_t)(prow * PROW + j0 * 2);
                *reinterpret_cast<uint4*>(ab + PHI_OFF(buf) + ro) =
                    make_uint4(hiu[0], hiu[1], hiu[2], hiu[3]);
                *reinterpret_cast<uint4*>(ab + PHI_OFF(buf) + ro + 16) =
                    make_uint4(hiu[4], hiu[5], hiu[6], hiu[7]);
            }
            bar_arrive(1 + buf);                   // buffer full
            // prefetch next tile (wrap keeps addresses valid)
            {
                const int nt = (it + 1 < NTILES) ? it + 1 : 0;
                const uint4* mp = mrow_p + nt * 16;
                #pragma unroll
                for (int g = 0; g < 4; g++) mreg[g] = mp[g];
                hA = *reinterpret_cast<const uint4*>(hbase + nt * 64);
                hB = *reinterpret_cast<const uint4*>(hbase + nt * 64 + 8);
            }
        }
    } else {
        // ================= CONSUMER loop =================
        for (int it = 0; it < NTILES; it++) {
            const int buf = it & 1;
            bar_sync(1 + buf);                     // wait buffer full
            const uint32_t phi = abase + PHI_OFF(buf);
            const uint32_t bhi = abase + BHI_OFF(buf);
            #pragma unroll
            for (int kk = 0; kk < 4; kk++) {
                const uint32_t off = (uint32_t)(kk * 32);
                uint32_t ah[4], bh0[4], bh1[4];
                ldsm_x4(ah, phi + a_base + off);
                ldsm_x4(bh0, bhi + b_base0 + off);
                ldsm_x4(bh1, bhi + b_base1 + off);
                mma16816(acc[0], ah, &bh0[0]);
                mma16816(acc[1], ah, &bh0[2]);
                mma16816(acc[2], ah, &bh1[0]);
                mma16816(acc[3], ah, &bh1[2]);
            }
            bar_arrive(3 + buf);                   // buffer free
        }
    }

    // ---- epilogue ----
    if (w < 8) {
        float zlo, zhi;
        upk2(zlo, zhi, zacc);
        float zsum = zlo + zhi;
        zsum += __shfl_xor_sync(0xffffffffu, zsum, 1);
        zsum += __shfl_xor_sync(0xffffffffu, zsum, 2);
        if ((t & 3) == 0) zs[prow] = zsum;
    }
    __syncthreads();
    if (w >= 8) {
        const int r0 = mrow + (lane >> 2);
        const float rz0 = 1.0f / zs[r0];
        const float rz1 = 1.0f / zs[r0 + 8];
        #pragma unroll
        for (int nf = 0; nf < 4; nf++) {
            const int col = nc0 + nf * 8 + (lane & 3) * 2;
            *reinterpret_cast<float2*>(
                out + (size_t)(ibase + r0) * D_OUT + col) =
                make_float2(acc[nf][0] * rz0, acc[nf][1] * rz0);
            *reinterpret_cast<float2*>(
                out + (size_t)(ibase + r0 + 8) * D_OUT + col) =
                make_float2(acc[nf][2] * rz1, acc[nf][3] * rz1);
        }
    }
}

// ---------------- launch ----------------
extern "C" void kernel_launch(void* const* d_in, const int* in_sizes, int n_in,
                              void* d_out, int out_size) {
    const float* x     = (const float*)d_in[0];   // [8192, 256]
    const int*   mask  = (const int*)d_in[1];     // [8192, 8192]
    const float* trans = (const float*)d_in[2];   // [256, 64]
    const float* attn  = (const float*)d_in[3];   // [128, 1]
    float* out = (float*)d_out;                   // [8192, 64]

    cudaFuncSetAttribute(k_attn_ws, cudaFuncAttributeMaxDynamicSharedMemorySize,
                         SMEM_BYTES);

    k_h_gemm<<<N_NODES / 16, 256>>>(x, trans);
    k_e<<<N_NODES / 8, 256>>>(attn);
    k_attn_ws<<<N_NODES / 64, 512, SMEM_BYTES>>>(mask, out);
}

// round 10
// speedup vs baseline: 1.6060x; 1.2687x over previous
#include <cuda_runtime.h>
#include <cuda_fp16.h>
#include <cstdint>

// ---------------- problem constants ----------------
#define N_NODES 8192
#define F_IN    256
#define D_OUT   64
#define LOG2E   1.4426950408889634f
#define PSCALE  0x1p-8f   // global 2^-8 on P; cancels in softmax

// ---------------- device scratch (no allocation allowed) ----------------
__device__ float g_h[N_NODES * D_OUT];
__device__ float g_e1[N_NODES];
__device__ float g_e2[N_NODES];
__device__ __half g_ht[D_OUT * N_NODES];    // H^T fp16, [d][j]

// ---------------- helpers ----------------
__device__ __forceinline__ uint32_t smem_u32(const void* p) {
    uint32_t a;
    asm("{ .reg .u64 t; cvta.to.shared.u64 t, %1; cvt.u32.u64 %0, t; }"
        : "=r"(a) : "l"(p));
    return a;
}
__device__ __forceinline__ uint32_t pack_f16x2(float lo, float hi) {
    uint32_t r;
    asm("cvt.rn.f16x2.f32 %0, %1, %2;" : "=r"(r) : "f"(hi), "f"(lo));
    return r;
}
__device__ __forceinline__ float ex2(float x) {
    float r;
    asm("ex2.approx.ftz.f32 %0, %1;" : "=f"(r) : "f"(x));
    return r;
}
__device__ __forceinline__ unsigned long long pk2(float lo, float hi) {
    unsigned long long r;
    asm("mov.b64 %0, {%1, %2};" : "=l"(r) : "f"(lo), "f"(hi));
    return r;
}
__device__ __forceinline__ void upk2(float& lo, float& hi, unsigned long long v) {
    asm("mov.b64 {%0, %1}, %2;" : "=f"(lo), "=f"(hi) : "l"(v));
}
__device__ __forceinline__ void add2(unsigned long long& d, unsigned long long a) {
    asm("add.rn.f32x2 %0, %0, %1;" : "+l"(d) : "l"(a));
}
__device__ __forceinline__ void ldsm_x4(uint32_t (&r)[4], uint32_t addr) {
    asm volatile("ldmatrix.sync.aligned.m8n8.x4.shared.b16 {%0,%1,%2,%3}, [%4];"
                 : "=r"(r[0]), "=r"(r[1]), "=r"(r[2]), "=r"(r[3]) : "r"(addr));
}
__device__ __forceinline__ void mma16816(float (&c)[4], const uint32_t (&a)[4],
                                         const uint32_t* b) {
    asm volatile("mma.sync.aligned.m16n8k16.row.col.f32.f16.f16.f32 "
        "{%0,%1,%2,%3}, {%4,%5,%6,%7}, {%8,%9}, {%0,%1,%2,%3};"
        : "+f"(c[0]), "+f"(c[1]), "+f"(c[2]), "+f"(c[3])
        : "r"(a[0]), "r"(a[1]), "r"(a[2]), "r"(a[3]), "r"(b[0]), "r"(b[1]));
}

// ---------------- kernel 1: h = x @ trans ----------------
__global__ void k_h_gemm(const float* __restrict__ x,
                         const float* __restrict__ trans) {
    __shared__ float xs[16 * F_IN];
    __shared__ float ts[64 * D_OUT];
    __shared__ float trs[64 * 17];

    const int t = threadIdx.x;
    const int d = t & 63;
    const int rg = t >> 6;
    const int ibase = blockIdx.x * 16;

    {
        const float4* xg4 = reinterpret_cast<const float4*>(x) + (size_t)ibase * (F_IN / 4);
        float4* xs4 = reinterpret_cast<float4*>(xs);
        #pragma unroll
        for (int q = 0; q < 4; q++) xs4[t + q * 256] = xg4[t + q * 256];
    }

    float acc[4] = {0.f, 0.f, 0.f, 0.f};

    for (int kc = 0; kc < 4; kc++) {
        {
            const float4* tg4 = reinterpret_cast<const float4*>(trans) + kc * 1024;
            float4* ts4 = reinterpret_cast<float4*>(ts);
            #pragma unroll
            for (int q = 0; q < 4; q++) ts4[t + q * 256] = tg4[t + q * 256];
        }
        __syncthreads();
        #pragma unroll 4
        for (int k4 = 0; k4 < 16; k4++) {
            float4 xv[4];
            #pragma unroll
            for (int r = 0; r < 4; r++)
                xv[r] = *reinterpret_cast<const float4*>(
                    &xs[(rg * 4 + r) * F_IN + kc * 64 + k4 * 4]);
            #pragma unroll
            for (int kk = 0; kk < 4; kk++) {
                const float tv = ts[(k4 * 4 + kk) * 64 + d];
                #pragma unroll
                for (int r = 0; r < 4; r++)
                    acc[r] = fmaf(reinterpret_cast<const float*>(&xv[r])[kk],
                                  tv, acc[r]);
            }
        }
        __syncthreads();
    }

    #pragma unroll
    for (int r = 0; r < 4; r++) {
        g_h[(size_t)(ibase + rg * 4 + r) * D_OUT + d] = acc[r];
        trs[d * 17 + rg * 4 + r] = acc[r];
    }
    __syncthreads();

    {
        const int dd = t >> 2;
        const int seg = t & 3;
        const float v0 = trs[dd * 17 + seg * 4 + 0];
        const float v1 = trs[dd * 17 + seg * 4 + 1];
        const float v2 = trs[dd * 17 + seg * 4 + 2];
        const float v3 = trs[dd * 17 + seg * 4 + 3];
        const uint32_t h01 = pack_f16x2(v0, v1);
        const uint32_t h23 = pack_f16x2(v2, v3);
        *reinterpret_cast<uint2*>(g_ht + (size_t)dd * N_NODES + ibase + seg * 4) =
            make_uint2(h01, h23);
    }
}

// ---------------- kernel 2: e1/e2 projections ----------------
__global__ void k_e(const float* __restrict__ attn) {
    const int wid = threadIdx.x >> 5;
    const int lane = threadIdx.x & 31;
    const int row = blockIdx.x * 8 + wid;

    const float h0 = g_h[(size_t)row * D_OUT + lane];
    const float h1 = g_h[(size_t)row * D_OUT + lane + 32];
    float v1 = h0 * attn[lane] + h1 * attn[lane + 32];
    float v2 = h0 * attn[64 + lane] + h1 * attn[96 + lane];
    #pragma unroll
    for (int o = 16; o > 0; o >>= 1) {
        v1 += __shfl_xor_sync(0xffffffffu, v1, o);
        v2 += __shfl_xor_sync(0xffffffffu, v2, o);
    }
    if (lane == 0) { g_e1[row] = v1; g_e2[row] = v2; }
}

// ---------------- kernel 3: warp-specialized attention, 2 CTAs/SM ----------------
// CTA: 32 rows x full 8192 j. Tile: 32 rows x 64 j. 128 tiles. 256 CTAs.
#define ROWS 32
#define PROW 144
#define PHI_OFF(b) ((b) * 4608)               // P: 2 x 4.5 KB (32 x 144)
#define BHI_OFF(b) (9216 + (b) * 9216)        // H: 2 x 9 KB (64 x 144)
#define SMEM_BYTES (9216 + 18432 + 128)

#define NTILES 128

__global__ __launch_bounds__(512, 2)
void k_attn_ws(const int* __restrict__ mask,
               const float* __restrict__ e2g,
               float* __restrict__ out) {
    extern __shared__ char dsmem[];
    __shared__ float zs[ROWS];

    const int t = threadIdx.x;
    const int lane = t & 31;
    const int w = t >> 5;
    const int ibase = blockIdx.x * ROWS;

    const uint32_t sbase = smem_u32(dsmem);
    const uint32_t abase = (sbase + 127) & ~127u;
    char* ab = dsmem + (abase - sbase);

    // ============ producer state (warps 0-7, t < 256) ============
    const int prow = t >> 3;            // row within block (0..31)
    const int j0 = (t & 7) << 3;        // 8 j per thread
    const float ei = g_e1[ibase + prow] * LOG2E;

    const uint4* mrow_p = reinterpret_cast<const uint4*>(
        mask + (size_t)(ibase + prow) * N_NODES + j0);   // tile stride: 16 uint4
    const int hd = t >> 2;              // d row 0..63
    const int hj = t & 3;               // j segment *16
    const __half* hbase = g_ht + (size_t)hd * N_NODES + hj * 16;

    uint4 mreg[2];
    uint4 hA, hB;
    unsigned long long zacc = 0ull;

    // ============ consumer state (warps 8-15) ============
    const int wc = w - 8;
    const int mrow = (wc & 1) * 16;     // 2 m-groups of 16
    const int nc0 = (wc >> 1) * 16;     // 4 n-groups of 16
    const uint32_t a_base = (uint32_t)((mrow + (lane & 15)) * PROW + ((lane >> 4) << 4));
    const uint32_t b_base = (uint32_t)(
        (nc0 + ((lane >> 4) << 3) + (lane & 7)) * PROW + (((lane >> 3) & 1) << 4));

    float acc[2][4];
    #pragma unroll
    for (int nf = 0; nf < 2; nf++)
        #pragma unroll
        for (int c = 0; c < 4; c++) acc[nf][c] = 0.f;

    // prologue prefetch (producers, tile 0)
    if (w < 8) {
        mreg[0] = mrow_p[0];
        mreg[1] = mrow_p[1];
        hA = *reinterpret_cast<const uint4*>(hbase);
        hB = *reinterpret_cast<const uint4*>(hbase + 8);
    }

    for (int it = 0; it <= NTILES; it++) {
        __syncthreads();
        if (w < 8) {
            if (it < NTILES) {
                const int buf = it & 1;
                // stage H tile
                {
                    const uint32_t so = (uint32_t)(hd * PROW + hj * 32);
                    *reinterpret_cast<uint4*>(ab + BHI_OFF(buf) + so) = hA;
                    *reinterpret_cast<uint4*>(ab + BHI_OFF(buf) + so + 16) = hB;
                }
                // compute P (8 elems), single fp16
                {
                    const float4* e2p = reinterpret_cast<const float4*>(
                        e2g + it * 64 + j0);
                    uint32_t hiu[4];
                    #pragma unroll
                    for (int g = 0; g < 2; g++) {
                        const float4 ev = __ldg(e2p + g);
                        const uint4 mm = mreg[g];
                        const float e4[4] = {ev.x, ev.y, ev.z, ev.w};
                        const uint32_t m4[4] = {mm.x, mm.y, mm.z, mm.w};
                        float p[4];
                        #pragma unroll
                        for (int k = 0; k < 4; k++) {
                            float s = fmaf(e4[k], LOG2E, ei);
                            s = fmaxf(s, 0.2f * s);
                            const float pe = ex2(s) * PSCALE;
                            p[k] = __uint_as_float(__float_as_uint(pe) &
                                                   (uint32_t)(-(int)m4[k]));
                        }
                        add2(zacc, pk2(p[0], p[1]));
                        add2(zacc, pk2(p[2], p[3]));
                        hiu[g * 2]     = pack_f16x2(p[0], p[1]);
                        hiu[g * 2 + 1] = pack_f16x2(p[2], p[3]);
                    }
                    const uint32_t ro = (uint32_t)(prow * PROW + j0 * 2);
                    *reinterpret_cast<uint4*>(ab + PHI_OFF(buf) + ro) =
                        make_uint4(hiu[0], hiu[1], hiu[2], hiu[3]);
                }
                // prefetch next tile (wrap keeps addresses valid)
                {
                    const int nt = (it + 1 < NTILES) ? it + 1 : 0;
                    const uint4* mp = mrow_p + nt * 16;
                    mreg[0] = mp[0];
                    mreg[1] = mp[1];
                    hA = *reinterpret_cast<const uint4*>(hbase + nt * 64);
                    hB = *reinterpret_cast<const uint4*>(hbase + nt * 64 + 8);
                }
            }
        } else {
            if (it >= 1) {
                const int buf = (it - 1) & 1;
                const uint32_t phi = abase + PHI_OFF(buf);
                const uint32_t bhi = abase + BHI_OFF(buf);
                #pragma unroll
                for (int kk = 0; kk < 4; kk++) {
                    const uint32_t off = (uint32_t)(kk * 32);
                    uint32_t ah[4], bh[4];
                    ldsm_x4(ah, phi + a_base + off);
                    ldsm_x4(bh, bhi + b_base + off);
                    mma16816(acc[0], ah, &bh[0]);
                    mma16816(acc[1], ah, &bh[2]);
                }
            }
        }
    }

    // ---- epilogue ----
    if (w < 8) {
        float zlo, zhi;
        upk2(zlo, zhi, zacc);
        float zsum = zlo + zhi;
        zsum += __shfl_xor_sync(0xffffffffu, zsum, 1);
        zsum += __shfl_xor_sync(0xffffffffu, zsum, 2);
        zsum += __shfl_xor_sync(0xffffffffu, zsum, 4);
        if ((t & 7) == 0) zs[prow] = zsum;
    }
    __syncthreads();
    if (w >= 8) {
        const int r0 = mrow + (lane >> 2);
        const float rz0 = 1.0f / zs[r0];
        const float rz1 = 1.0f / zs[r0 + 8];
        #pragma unroll
        for (int nf = 0; nf < 2; nf++) {
            const int col = nc0 + nf * 8 + (lane & 3) * 2;
            *reinterpret_cast<float2*>(
                out + (size_t)(ibase + r0) * D_OUT + col) =
                make_float2(acc[nf][0] * rz0, acc[nf][1] * rz0);
            *reinterpret_cast<float2*>(
                out + (size_t)(ibase + r0 + 8) * D_OUT + col) =
                make_float2(acc[nf][2] * rz1, acc[nf][3] * rz1);
        }
    }
}

// ---------------- launch ----------------
extern "C" void kernel_launch(void* const* d_in, const int* in_sizes, int n_in,
                              void* d_out, int out_size) {
    const float* x     = (const float*)d_in[0];   // [8192, 256]
    const int*   mask  = (const int*)d_in[1];     // [8192, 8192]
    const float* trans = (const float*)d_in[2];   // [256, 64]
    const float* attn  = (const float*)d_in[3];   // [128, 1]
    float* out = (float*)d_out;                   // [8192, 64]

    cudaFuncSetAttribute(k_attn_ws, cudaFuncAttributeMaxDynamicSharedMemorySize,
                         SMEM_BYTES);

    k_h_gemm<<<N_NODES / 16, 256>>>(x, trans);
    k_e<<<N_NODES / 8, 256>>>(attn);

    float* e2g;
    cudaGetSymbolAddress((void**)&e2g, g_e2);
    k_attn_ws<<<N_NODES / ROWS, 512, SMEM_BYTES>>>(mask, e2g, out);
}